// round 4
// baseline (speedup 1.0000x reference)
#include <cuda_runtime.h>
#include <cuda_bf16.h>
#include <cstdint>

// MarginRankingLoss: x [V=4096, C=128, T=128] f32, target [V, C] int (32 or 64 bit).
// loss = sum_{v,c,t != tgt} max(0, x[v,c,t] - x[v,c,tgt] + 0.5) / (V*C*(T-1))
//
// Trick: target position contributes exactly max(0, 0.5) = 0.5, so sum over
// ALL t (branch-free, fully vectorized) and subtract ROWS*0.5 at the end.

static constexpr long long V = 4096;
static constexpr long long C = 128;
static constexpr int       T = 128;
static constexpr long long ROWS = V * C;          // 524288
static constexpr float     MARGIN = 0.5f;

__device__ double g_acc;
__device__ int    g_tgt_is64;

// Zero accumulator + detect target element width.
// int64 targets in [0,128): every odd 32-bit word is a zero high-half.
// int32 targets: odd words are random values in [0,128) -> P(all zero) ~ 0.
__global__ void mrl_init_kernel(const int* __restrict__ tgt32) {
    g_acc = 0.0;
    int all_zero = 1;
    #pragma unroll 1
    for (int i = 1; i < 128; i += 2) {
        if (tgt32[i] != 0) { all_zero = 0; break; }
    }
    g_tgt_is64 = all_zero;
}

__global__ void __launch_bounds__(256) mrl_main_kernel(
    const float* __restrict__ x,
    const void* __restrict__ tgt_raw)
{
    const int lane  = threadIdx.x & 31;
    const int gwarp = (int)((blockIdx.x * blockDim.x + threadIdx.x) >> 5);
    const int nwarp = (int)((gridDim.x * blockDim.x) >> 5);

    const float4*    __restrict__ x4    = reinterpret_cast<const float4*>(x);
    const int*       __restrict__ tgt32 = reinterpret_cast<const int*>(tgt_raw);
    const long long* __restrict__ tgt64 = reinterpret_cast<const long long*>(tgt_raw);
    const int is64 = g_tgt_is64;

    float s = 0.0f;
    for (long long row = gwarp; row < ROWS; row += nwarp) {
        int t = is64 ? (int)tgt64[row] : tgt32[row];  // broadcast load
        t &= (T - 1);                                  // never fault
        const float pos = x[row * T + t];              // broadcast load
        const float b = pos - MARGIN;                  // hinge = max(0, v - b)
        const float4 v = x4[row * 32 + lane];          // coalesced LDG.128
        s += fmaxf(v.x - b, 0.0f);
        s += fmaxf(v.y - b, 0.0f);
        s += fmaxf(v.z - b, 0.0f);
        s += fmaxf(v.w - b, 0.0f);
    }

    // warp reduce
    #pragma unroll
    for (int o = 16; o > 0; o >>= 1)
        s += __shfl_xor_sync(0xffffffffu, s, o);

    __shared__ double warp_sums[8];
    const int wid = threadIdx.x >> 5;
    if (lane == 0) warp_sums[wid] = (double)s;
    __syncthreads();

    if (threadIdx.x == 0) {
        double bs = 0.0;
        #pragma unroll
        for (int i = 0; i < 8; i++) bs += warp_sums[i];
        atomicAdd(&g_acc, bs);
    }
}

__global__ void mrl_finalize_kernel(float* __restrict__ out) {
    // subtract the target positions' contribution (exactly MARGIN each),
    // then normalize by V*C*(T-1)
    const double total = g_acc - (double)ROWS * (double)MARGIN;
    out[0] = (float)(total / ((double)ROWS * (double)(T - 1)));
}

extern "C" void kernel_launch(void* const* d_in, const int* in_sizes, int n_in,
                              void* d_out, int out_size)
{
    const float* x   = (const float*)d_in[0];
    const void*  tgt = d_in[1];
    float*       out = (float*)d_out;

    mrl_init_kernel<<<1, 1>>>((const int*)tgt);
    mrl_main_kernel<<<2048, 256>>>(x, tgt);
    mrl_finalize_kernel<<<1, 1>>>(out);
}